// round 4
// baseline (speedup 1.0000x reference)
#include <cuda_runtime.h>
#include <cuda_bf16.h>
#include <cstdint>

// Sparsemax along last dim of a [ROWS, 32000] fp32 matrix.
//
// Exact, sort-free: tau solves sum_i max(x_i - tau, 0) = 1, tau >= rowmax-1,
// so the support is contained in C = {x > rowmax-1} (~25 elems/row Gaussian).
//
// Persistent CTAs. Row data streams through an 8-stage x 16KB SMEM ring via
// cp.async.bulk (TMA) with per-chunk mbarrier full/empty pairs; prefetch
// distance = 1 row, so TMA runs continuously across row boundaries while
// registers hold the current row. Per row only 2 block barriers:
//   barrier A after shared atomicMax (rowmax), barrier B after compaction.
// All warps redundantly run Michelot on the candidate list (no broadcast).

#define SMX_N        32000
#define SMX_THREADS  1024
#define SMX_NCH      8            // chunks per row
#define SMX_CHF4     1024         // float4 per chunk (16KB)
#define SMX_CHBYTES  16384
#define SMX_LASTF4   832          // last chunk: 8000-7*1024 float4
#define SMX_LASTB    13312
#define SMX_NEG      (-3.0e38f)
#define SMX_CAP      2048

__device__ __forceinline__ uint32_t smx_smem_u32(const void* p) {
    uint32_t a;
    asm("{ .reg .u64 t; cvta.to.shared.u64 t, %1; cvt.u32.u64 %0, t; }"
        : "=r"(a) : "l"(p));
    return a;
}
__device__ __forceinline__ void smx_mbar_init(uint32_t mbar, uint32_t count) {
    asm volatile("mbarrier.init.shared.b64 [%0], %1;" :: "r"(mbar), "r"(count) : "memory");
}
__device__ __forceinline__ void smx_expect_tx(uint32_t mbar, uint32_t bytes) {
    asm volatile("mbarrier.arrive.expect_tx.shared.b64 _, [%0], %1;"
                 :: "r"(mbar), "r"(bytes) : "memory");
}
__device__ __forceinline__ void smx_arrive(uint32_t mbar) {
    asm volatile("mbarrier.arrive.shared.b64 _, [%0];" :: "r"(mbar) : "memory");
}
__device__ __forceinline__ void smx_bulk_g2s(uint32_t dst, const void* src,
                                             uint32_t bytes, uint32_t mbar) {
    asm volatile(
        "cp.async.bulk.shared::cta.global.mbarrier::complete_tx::bytes [%0], [%1], %2, [%3];"
        :: "r"(dst), "l"(src), "r"(bytes), "r"(mbar) : "memory");
}
__device__ __forceinline__ void smx_mbar_wait(uint32_t mbar, uint32_t parity) {
    asm volatile(
        "{\n\t"
        ".reg .pred P;\n\t"
        "SMXW%=:\n\t"
        "mbarrier.try_wait.parity.acquire.cta.shared::cta.b64 P, [%0], %1, 0x989680;\n\t"
        "@P bra SMXD%=;\n\t"
        "bra SMXW%=;\n\t"
        "SMXD%=:\n\t"
        "}"
        :: "r"(mbar), "r"(parity) : "memory");
}

// order-preserving float<->uint for shared atomicMax
__device__ __forceinline__ unsigned smx_enc(float f) {
    unsigned b = __float_as_uint(f);
    return (b & 0x80000000u) ? ~b : (b | 0x80000000u);
}
__device__ __forceinline__ float smx_dec(unsigned u) {
    return (u & 0x80000000u) ? __uint_as_float(u & 0x7fffffffu)
                             : __uint_as_float(~u);
}

extern __shared__ float smx_buf[];   // 8 stages * 4096 floats = 128 KB

__global__ __launch_bounds__(SMX_THREADS, 1)
void sparsemax_kernel(const float* __restrict__ x, float* __restrict__ y, int rows) {
    const int t    = threadIdx.x;
    const int lane = t & 31;
    const int stride = gridDim.x;

    __shared__ __align__(8) uint64_t s_full[SMX_NCH];
    __shared__ __align__(8) uint64_t s_empty[SMX_NCH];
    __shared__ unsigned s_maxbits[2];
    __shared__ int      s_cnt[2];
    __shared__ float    s_red[2][2];      // fallback accumulators [iter parity][sum,cnt]
    __shared__ float    s_cand[2][SMX_CAP];

    const uint32_t fullb  = smx_smem_u32(s_full);
    const uint32_t emptyb = smx_smem_u32(s_empty);

    if (t == 0) {
        #pragma unroll
        for (int s = 0; s < SMX_NCH; s++) {
            smx_mbar_init(fullb + 8u * s, 1);      // expect_tx arrive + tx bytes
            smx_mbar_init(emptyb + 8u * s, 32);    // one arrive per warp
        }
        s_maxbits[0] = 0u;  s_cnt[0] = 0;
    }
    __syncthreads();

    const int row0 = blockIdx.x;
    if (row0 >= rows) return;
    const int nrows = (rows - 1 - row0) / stride + 1;
    const int total = nrows * SMX_NCH;

    // prologue: fill the ring (one row ahead)
    if (t == 0) {
        const int pre = total < SMX_NCH ? total : SMX_NCH;
        for (int c = 0; c < pre; c++) {
            const int rr = c >> 3, i = c & 7;
            const size_t row = (size_t)(row0 + rr * stride);
            const uint32_t bytes = (i == 7) ? SMX_LASTB : SMX_CHBYTES;
            smx_expect_tx(fullb + 8u * c, bytes);
            smx_bulk_g2s(smx_smem_u32(smx_buf + c * (SMX_CHF4 * 4)),
                         x + row * SMX_N + (size_t)i * (SMX_CHF4 * 4), bytes,
                         fullb + 8u * c);
        }
    }

    unsigned p = 0;   // row parity for scratch slots

    for (int rr = 0; rr < nrows; rr++) {
        const int row = row0 + rr * stride;

        // ---- consume 8 chunks into registers, fused running max ----
        float4 v[SMX_NCH];
        float m = SMX_NEG;
        #pragma unroll
        for (int i = 0; i < SMX_NCH; i++) {
            const int c  = rr * SMX_NCH + i;
            const int s  = c & 7;
            const uint32_t ph = (unsigned)(c >> 3) & 1u;
            smx_mbar_wait(fullb + 8u * s, ph);
            const float4* sb = reinterpret_cast<const float4*>(smx_buf + s * (SMX_CHF4 * 4));
            if (i < 7 || t < SMX_LASTF4) {
                v[i] = sb[t];
                m = fmaxf(m, fmaxf(fmaxf(v[i].x, v[i].y), fmaxf(v[i].z, v[i].w)));
            } else {
                v[i] = make_float4(SMX_NEG, SMX_NEG, SMX_NEG, SMX_NEG);
            }
            __syncwarp();
            if (lane == 0) smx_arrive(emptyb + 8u * s);   // release stage (per warp)
            // t0: refill this stage with the chunk one row ahead
            if (t == 0) {
                const int cp = c + SMX_NCH;
                if (cp < total) {
                    smx_mbar_wait(emptyb + 8u * s, (unsigned)(c >> 3) & 1u);
                    const int rr2 = cp >> 3, i2 = cp & 7;
                    const size_t row2 = (size_t)(row0 + rr2 * stride);
                    const uint32_t bytes = (i2 == 7) ? SMX_LASTB : SMX_CHBYTES;
                    smx_expect_tx(fullb + 8u * s, bytes);
                    smx_bulk_g2s(smx_smem_u32(smx_buf + s * (SMX_CHF4 * 4)),
                                 x + row2 * SMX_N + (size_t)i2 * (SMX_CHF4 * 4), bytes,
                                 fullb + 8u * s);
                }
            }
        }

        // ---- rowmax via warp reduce + shared atomicMax ----
        #pragma unroll
        for (int o = 16; o; o >>= 1)
            m = fmaxf(m, __shfl_xor_sync(0xffffffffu, m, o));
        if (lane == 0) atomicMax(&s_maxbits[p], smx_enc(m));
        __syncthreads();                                  // barrier A
        const float thr = smx_dec(s_maxbits[p]) - 1.0f;   // tau >= thr always
        if (t == 0) { s_maxbits[p ^ 1] = 0u; s_cnt[p ^ 1] = 0; }  // prep next row

        // ---- compact candidates {x > thr} ----
        #pragma unroll
        for (int i = 0; i < SMX_NCH; i++) {
            const float a0 = v[i].x, a1 = v[i].y, a2 = v[i].z, a3 = v[i].w;
            if (a0 > thr) { int k = atomicAdd(&s_cnt[p], 1); if (k < SMX_CAP) s_cand[p][k] = a0; }
            if (a1 > thr) { int k = atomicAdd(&s_cnt[p], 1); if (k < SMX_CAP) s_cand[p][k] = a1; }
            if (a2 > thr) { int k = atomicAdd(&s_cnt[p], 1); if (k < SMX_CAP) s_cand[p][k] = a2; }
            if (a3 > thr) { int k = atomicAdd(&s_cnt[p], 1); if (k < SMX_CAP) s_cand[p][k] = a3; }
        }
        __syncthreads();                                  // barrier B
        const int cnt = s_cnt[p];

        float tau;
        if (cnt <= SMX_CAP) {
            // ---- every warp redundantly: Michelot on candidate list ----
            tau = thr;
            float prevc = -1.0f;
            #pragma unroll 1
            for (int it = 0; it < 64; it++) {
                float s = 0.0f, c = 0.0f;
                for (int j = lane; j < cnt; j += 32) {
                    const float z = s_cand[p][j];
                    if (z > tau) { s += z; c += 1.0f; }
                }
                #pragma unroll
                for (int o = 16; o; o >>= 1) {
                    s += __shfl_xor_sync(0xffffffffu, s, o);
                    c += __shfl_xor_sync(0xffffffffu, c, o);
                }
                tau = (s - 1.0f) / c;
                if (c == prevc) break;                    // fixed point: exact tau
                prevc = c;
            }
        } else {
            // ---- fallback: full-row Michelot via shared atomics (rare) ----
            if (t == 0) { s_red[0][0] = 0.f; s_red[0][1] = 0.f;
                          s_red[1][0] = 0.f; s_red[1][1] = 0.f; }
            __syncthreads();
            tau = thr;
            float prevc = -1.0f;
            unsigned q = 0;
            #pragma unroll 1
            for (int it = 0; it < 64; it++) {
                float s = 0.0f, c = 0.0f;
                #pragma unroll
                for (int i = 0; i < SMX_NCH; i++) {
                    if (v[i].x > tau) { s += v[i].x; c += 1.0f; }
                    if (v[i].y > tau) { s += v[i].y; c += 1.0f; }
                    if (v[i].z > tau) { s += v[i].z; c += 1.0f; }
                    if (v[i].w > tau) { s += v[i].w; c += 1.0f; }
                }
                #pragma unroll
                for (int o = 16; o; o >>= 1) {
                    s += __shfl_xor_sync(0xffffffffu, s, o);
                    c += __shfl_xor_sync(0xffffffffu, c, o);
                }
                if (lane == 0) { atomicAdd(&s_red[q][0], s); atomicAdd(&s_red[q][1], c); }
                if (t == 0) { s_red[q ^ 1][0] = 0.f; s_red[q ^ 1][1] = 0.f; }
                __syncthreads();
                const float S = s_red[q][0], C = s_red[q][1];
                __syncthreads();   // all reads done before next iter's accumulate
                tau = (S - 1.0f) / C;
                if (C == prevc) break;
                prevc = C;
                q ^= 1;
            }
        }

        // ---- output: max(x - tau, 0), coalesced STG.128 ----
        float4* __restrict__ yr = reinterpret_cast<float4*>(y + (size_t)row * SMX_N);
        #pragma unroll
        for (int i = 0; i < 7; i++) {
            float4 o;
            o.x = fmaxf(v[i].x - tau, 0.0f);
            o.y = fmaxf(v[i].y - tau, 0.0f);
            o.z = fmaxf(v[i].z - tau, 0.0f);
            o.w = fmaxf(v[i].w - tau, 0.0f);
            yr[i * SMX_CHF4 + t] = o;
        }
        if (t < SMX_LASTF4) {
            float4 o;
            o.x = fmaxf(v[7].x - tau, 0.0f);
            o.y = fmaxf(v[7].y - tau, 0.0f);
            o.z = fmaxf(v[7].z - tau, 0.0f);
            o.w = fmaxf(v[7].w - tau, 0.0f);
            yr[7 * SMX_CHF4 + t] = o;
        }

        p ^= 1u;
    }
}

extern "C" void kernel_launch(void* const* d_in, const int* in_sizes, int n_in,
                              void* d_out, int out_size) {
    const float* x = (const float*)d_in[0];
    float* y = (float*)d_out;
    const int rows = in_sizes[0] / SMX_N;

    int dev = 0, sms = 148;
    cudaGetDevice(&dev);
    cudaDeviceGetAttribute(&sms, cudaDevAttrMultiProcessorCount, dev);

    static bool attr_done = false;
    if (!attr_done) {
        cudaFuncSetAttribute(sparsemax_kernel,
                             cudaFuncAttributeMaxDynamicSharedMemorySize,
                             SMX_NCH * SMX_CHBYTES);
        attr_done = true;
    }

    int grid = rows < sms ? rows : sms;
    sparsemax_kernel<<<grid, SMX_THREADS, SMX_NCH * SMX_CHBYTES>>>(x, y, rows);
}